// round 1
// baseline (speedup 1.0000x reference)
#include <cuda_runtime.h>
#include <math.h>

#define D_DIM 256
#define N_SEQ 2048
#define BATCH 8
#define ROWS (BATCH * N_SEQ)   // 16384
#define HID   1024             // EXP * D
#define KT    32               // keys per attention tile

// ---------------- scratch (no allocations allowed) ----------------
__device__ float g_h  [ROWS * D_DIM];   // LN1(x)
__device__ float g_x1 [ROWS * D_DIM];   // x + SA
__device__ float g_h2 [ROWS * D_DIM];   // LN2(x1)
__device__ float g_mid[ROWS * HID];     // relu(h2@w1+b1)

// ---------------- LayerNorm: one block per row, D=256 threads ----------------
__global__ void __launch_bounds__(256) ln_kernel(const float* __restrict__ x,
                                                 const float* __restrict__ gamma,
                                                 const float* __restrict__ beta,
                                                 float* __restrict__ out) {
    int row = blockIdx.x;
    int t = threadIdx.x;
    float v = x[(size_t)row * D_DIM + t];
    float s = v, s2 = v * v;
    #pragma unroll
    for (int off = 16; off; off >>= 1) {
        s  += __shfl_xor_sync(0xffffffffu, s,  off);
        s2 += __shfl_xor_sync(0xffffffffu, s2, off);
    }
    __shared__ float ws[8], ws2[8], mv[2];
    int w = t >> 5, lane = t & 31;
    if (lane == 0) { ws[w] = s; ws2[w] = s2; }
    __syncthreads();
    if (t == 0) {
        float a = 0.f, b = 0.f;
        #pragma unroll
        for (int i = 0; i < 8; i++) { a += ws[i]; b += ws2[i]; }
        float mean = a * (1.0f / D_DIM);
        float var  = b * (1.0f / D_DIM) - mean * mean;
        mv[0] = mean;
        mv[1] = rsqrtf(var + 1e-5f);
    }
    __syncthreads();
    out[(size_t)row * D_DIM + t] = (v - mv[0]) * mv[1] * gamma[t] + beta[t];
}

// ---------------- Flash attention: 8 warps/block, warp = 1 query row ----------------
// h: LN1(x) used as Q=K=V.  x1 = x + softmax(h h^T / 16) h
__global__ void __launch_bounds__(256) attn_kernel(const float* __restrict__ h,
                                                   const float* __restrict__ x,
                                                   float* __restrict__ x1) {
    __shared__ float sK[KT * D_DIM];   // 32 KB key tile
    int tid  = threadIdx.x;
    int warp = tid >> 5, lane = tid & 31;
    int r = blockIdx.x * 8 + warp;               // global query row
    int b = r >> 11;                             // batch
    const float* hb = h + (size_t)b * N_SEQ * D_DIM;

    // q: lane owns elements [lane*8, lane*8+8)
    const float4* qp = (const float4*)(h + (size_t)r * D_DIM);
    float4 qa = qp[lane * 2];
    float4 qb = qp[lane * 2 + 1];

    float m = -1e30f, l = 0.f;
    float o[8];
    #pragma unroll
    for (int i = 0; i < 8; i++) o[i] = 0.f;

    for (int kt = 0; kt < N_SEQ / KT; kt++) {
        // cooperative SMEM fill: 2048 float4, 8 per thread, fully coalesced
        const float4* src = (const float4*)(hb + (size_t)kt * KT * D_DIM);
        float4* dst = (float4*)sK;
        #pragma unroll
        for (int i = 0; i < (KT * D_DIM / 4) / 256; i++)
            dst[tid + i * 256] = src[tid + i * 256];
        __syncthreads();

        #pragma unroll 4
        for (int j = 0; j < KT; j++) {
            const float4* kp = (const float4*)(sK + j * D_DIM);
            float4 ka = kp[lane * 2];
            float4 kb = kp[lane * 2 + 1];
            float d = qa.x * ka.x + qa.y * ka.y + qa.z * ka.z + qa.w * ka.w
                    + qb.x * kb.x + qb.y * kb.y + qb.z * kb.z + qb.w * kb.w;
            #pragma unroll
            for (int off = 16; off; off >>= 1)
                d += __shfl_xor_sync(0xffffffffu, d, off);
            float s = d * 0.0625f;           // 1/sqrt(256)
            if (s > m) {                      // warp-uniform branch (s replicated)
                float corr = __expf(m - s);   // first iter: exp(-inf)=0 -> clean init
                l *= corr;
                #pragma unroll
                for (int i = 0; i < 8; i++) o[i] *= corr;
                m = s;
            }
            float p = __expf(s - m);
            l += p;
            o[0] += p * ka.x; o[1] += p * ka.y; o[2] += p * ka.z; o[3] += p * ka.w;
            o[4] += p * kb.x; o[5] += p * kb.y; o[6] += p * kb.z; o[7] += p * kb.w;
        }
        __syncthreads();
    }

    float inv = 1.0f / l;
    const float4* xp = (const float4*)(x + (size_t)r * D_DIM);
    float4 xa = xp[lane * 2];
    float4 xb = xp[lane * 2 + 1];
    float4 oa = make_float4(xa.x + o[0] * inv, xa.y + o[1] * inv,
                            xa.z + o[2] * inv, xa.w + o[3] * inv);
    float4 ob = make_float4(xb.x + o[4] * inv, xb.y + o[5] * inv,
                            xb.z + o[6] * inv, xb.w + o[7] * inv);
    float4* op = (float4*)(x1 + (size_t)r * D_DIM);
    op[lane * 2]     = oa;
    op[lane * 2 + 1] = ob;
}

// ---------------- Tiled SGEMM: C[M,N] = A[M,K] @ B[K,N] (+bias) (+relu | +res) ----
// 64x64 tile, BK=16, 256 threads, 4x4 per thread.
__global__ void __launch_bounds__(256) sgemm_kernel(const float* __restrict__ A,
                                                    const float* __restrict__ Bm,
                                                    const float* __restrict__ bias,
                                                    const float* __restrict__ res,
                                                    float* __restrict__ C,
                                                    int N, int K, int do_relu) {
    __shared__ float As[16][68];   // padded: conflict-light transpose store, 16B aligned rows
    __shared__ float Bs[16][64];
    int tid = threadIdx.x;
    int bm = blockIdx.x, bn = blockIdx.y;

    int arow = tid >> 2;                 // 0..63
    int akq  = (tid & 3) * 4;            // 0,4,8,12
    int bk   = tid >> 4;                 // 0..15
    int bnq  = (tid & 15) * 4;           // 0..60
    int tx   = tid & 15, ty = tid >> 4;

    float acc[4][4];
    #pragma unroll
    for (int i = 0; i < 4; i++)
        #pragma unroll
        for (int j = 0; j < 4; j++) acc[i][j] = 0.f;

    const float* Aptr = A + (size_t)(bm * 64 + arow) * K + akq;
    const float* Bptr = Bm + (size_t)bk * N + bn * 64 + bnq;

    for (int k0 = 0; k0 < K; k0 += 16) {
        float4 a  = *(const float4*)(Aptr + k0);
        float4 bb = *(const float4*)(Bptr + (size_t)k0 * N);
        As[akq + 0][arow] = a.x;
        As[akq + 1][arow] = a.y;
        As[akq + 2][arow] = a.z;
        As[akq + 3][arow] = a.w;
        *(float4*)&Bs[bk][bnq] = bb;
        __syncthreads();

        #pragma unroll
        for (int k = 0; k < 16; k++) {
            float4 av = *(const float4*)&As[k][ty * 4];
            float4 bv = *(const float4*)&Bs[k][tx * 4];
            float ar[4] = {av.x, av.y, av.z, av.w};
            float br[4] = {bv.x, bv.y, bv.z, bv.w};
            #pragma unroll
            for (int i = 0; i < 4; i++)
                #pragma unroll
                for (int j = 0; j < 4; j++)
                    acc[i][j] += ar[i] * br[j];
        }
        __syncthreads();
    }

    #pragma unroll
    for (int i = 0; i < 4; i++) {
        int row = bm * 64 + ty * 4 + i;
        int col0 = bn * 64 + tx * 4;
        float4 v;
        float* vp = &v.x;
        #pragma unroll
        for (int j = 0; j < 4; j++) {
            float c = acc[i][j] + bias[col0 + j];
            if (do_relu) {
                c = fmaxf(c, 0.f);
            } else {
                c += res[(size_t)row * N + col0 + j];
            }
            vp[j] = c;
        }
        *(float4*)(C + (size_t)row * N + col0) = v;
    }
}

// ---------------- launch ----------------
extern "C" void kernel_launch(void* const* d_in, const int* in_sizes, int n_in,
                              void* d_out, int out_size) {
    const float* x   = (const float*)d_in[0];
    const float* w1  = (const float*)d_in[1];
    const float* b1  = (const float*)d_in[2];
    const float* w2  = (const float*)d_in[3];
    const float* b2  = (const float*)d_in[4];
    const float* g1  = (const float*)d_in[5];
    const float* be1 = (const float*)d_in[6];
    const float* g2  = (const float*)d_in[7];
    const float* be2 = (const float*)d_in[8];
    float* out = (float*)d_out;

    float *h, *x1, *h2, *mid;
    cudaGetSymbolAddress((void**)&h,   g_h);
    cudaGetSymbolAddress((void**)&x1,  g_x1);
    cudaGetSymbolAddress((void**)&h2,  g_h2);
    cudaGetSymbolAddress((void**)&mid, g_mid);

    // Sublayer 1
    ln_kernel<<<ROWS, 256>>>(x, g1, be1, h);
    attn_kernel<<<ROWS / 8, 256>>>(h, x, x1);

    // Sublayer 2
    ln_kernel<<<ROWS, 256>>>(x1, g2, be2, h2);
    sgemm_kernel<<<dim3(ROWS / 64, HID / 64), 256>>>(h2, w1, b1, nullptr, mid,
                                                     HID, D_DIM, 1);
    sgemm_kernel<<<dim3(ROWS / 64, D_DIM / 64), 256>>>(mid, w2, b2, x1, out,
                                                       D_DIM, HID, 0);
}

// round 2
// speedup vs baseline: 6.5870x; 6.5870x over previous
#include <cuda_runtime.h>
#include <math.h>
#include <stdint.h>

#define D_DIM 256
#define N_SEQ 2048
#define BATCH 8
#define ROWS (BATCH * N_SEQ)   // 16384
#define HID   1024

// ---------------- scratch ----------------
__device__ float g_h   [ROWS * D_DIM];            // LN1(x)
__device__ float g_hT  [BATCH * D_DIM * N_SEQ];   // per-batch transpose of h
__device__ float g_x1  [ROWS * D_DIM];            // x + SA
__device__ float g_h2  [ROWS * D_DIM];            // LN2(x1)
__device__ float g_mid [ROWS * HID];              // relu(h2@w1+b1)
__device__ float g_sc  [(size_t)BATCH * N_SEQ * N_SEQ];  // scores / probs (134MB)

// ---------------- helpers ----------------
__device__ __forceinline__ uint32_t f2tf(float f) {
    uint32_t u;
    asm("cvt.rna.tf32.f32 %0, %1;" : "=r"(u) : "f"(f));
    return u;
}

__device__ __forceinline__ void mma_tf32(float c[4], const uint32_t a[4], const uint32_t b[2]) {
    asm volatile("mma.sync.aligned.m16n8k8.row.col.f32.tf32.tf32.f32 "
                 "{%0,%1,%2,%3}, {%4,%5,%6,%7}, {%8,%9}, {%0,%1,%2,%3};"
                 : "+f"(c[0]), "+f"(c[1]), "+f"(c[2]), "+f"(c[3])
                 : "r"(a[0]), "r"(a[1]), "r"(a[2]), "r"(a[3]), "r"(b[0]), "r"(b[1]));
}

// ---------------- LayerNorm ----------------
__global__ void __launch_bounds__(256) ln_kernel(const float* __restrict__ x,
                                                 const float* __restrict__ gamma,
                                                 const float* __restrict__ beta,
                                                 float* __restrict__ out) {
    int row = blockIdx.x;
    int t = threadIdx.x;
    float v = x[(size_t)row * D_DIM + t];
    float s = v, s2 = v * v;
    #pragma unroll
    for (int off = 16; off; off >>= 1) {
        s  += __shfl_xor_sync(0xffffffffu, s,  off);
        s2 += __shfl_xor_sync(0xffffffffu, s2, off);
    }
    __shared__ float ws[8], ws2[8], mv[2];
    int w = t >> 5, lane = t & 31;
    if (lane == 0) { ws[w] = s; ws2[w] = s2; }
    __syncthreads();
    if (t == 0) {
        float a = 0.f, b = 0.f;
        #pragma unroll
        for (int i = 0; i < 8; i++) { a += ws[i]; b += ws2[i]; }
        float mean = a * (1.0f / D_DIM);
        float var  = b * (1.0f / D_DIM) - mean * mean;
        mv[0] = mean;
        mv[1] = rsqrtf(var + 1e-5f);
    }
    __syncthreads();
    out[(size_t)row * D_DIM + t] = (v - mv[0]) * mv[1] * gamma[t] + beta[t];
}

// ---------------- per-batch transpose: h[b][n][d] -> hT[b][d][n] ----------------
__global__ void __launch_bounds__(256) transpose_kernel(const float* __restrict__ src,
                                                        float* __restrict__ dst) {
    __shared__ float t[32][33];
    int b = blockIdx.z;
    int n0 = blockIdx.x * 32, d0 = blockIdx.y * 32;
    int tx = threadIdx.x & 31, ty = threadIdx.x >> 5;   // 32 x 8
    const float* s = src + (size_t)b * N_SEQ * D_DIM;
    float* d = dst + (size_t)b * D_DIM * N_SEQ;
    #pragma unroll
    for (int j = 0; j < 4; j++)
        t[ty + j * 8][tx] = s[(size_t)(n0 + ty + j * 8) * D_DIM + d0 + tx];
    __syncthreads();
    #pragma unroll
    for (int j = 0; j < 4; j++)
        d[(size_t)(d0 + ty + j * 8) * N_SEQ + n0 + tx] = t[tx][ty + j * 8];
}

// ---------------- tf32 tensor-core NN GEMM ----------------
// C[M,N] = alpha * A[M,K] @ B[K,N] (+bias[n]) (+relu) (+res)
// Tile 128x128x32, 256 threads, warp tile 64x32 (warps 2x4), m16n8k8 frags 4x4.
__global__ void __launch_bounds__(256) gemm_tf32(const float* __restrict__ A,
                                                 const float* __restrict__ B,
                                                 float* __restrict__ C,
                                                 const float* __restrict__ bias,
                                                 const float* __restrict__ res,
                                                 int N, int K, float alpha, int do_relu,
                                                 size_t sA, size_t sB, size_t sC) {
    __shared__ uint32_t As[128][36];   // bank (4m+k)%32 -> conflict-free frag loads
    __shared__ uint32_t Bs[32][136];   // bank (8k+n)%32 -> conflict-free frag loads

    int z = blockIdx.z;
    A += z * sA; B += z * sB; C += z * sC;
    const float* Rz = res ? res + z * sC : nullptr;

    int tid = threadIdx.x;
    int warp = tid >> 5, lane = tid & 31;
    int m0 = blockIdx.x * 128, n0 = blockIdx.y * 128;
    int wm = (warp >> 2) * 64;       // 0 or 64
    int wn = (warp & 3) * 32;        // 0..96
    int gr = lane >> 2, gc = lane & 3;

    float acc[4][4][4];
    #pragma unroll
    for (int i = 0; i < 4; i++)
        #pragma unroll
        for (int j = 0; j < 4; j++)
            #pragma unroll
            for (int v = 0; v < 4; v++) acc[i][j][v] = 0.f;

    int arow = tid >> 3, ak4 = tid & 7;      // A: 32 rows/pass x 8 float4
    int bkr  = tid >> 5, bn4 = tid & 31;     // B: 8 k-rows/pass x 32 float4

    for (int k0 = 0; k0 < K; k0 += 32) {
        #pragma unroll
        for (int i = 0; i < 4; i++) {
            int r = arow + i * 32;
            float4 v = *(const float4*)(A + (size_t)(m0 + r) * K + k0 + ak4 * 4);
            As[r][ak4 * 4 + 0] = f2tf(v.x);
            As[r][ak4 * 4 + 1] = f2tf(v.y);
            As[r][ak4 * 4 + 2] = f2tf(v.z);
            As[r][ak4 * 4 + 3] = f2tf(v.w);
        }
        #pragma unroll
        for (int i = 0; i < 4; i++) {
            int kr = bkr + i * 8;
            float4 v = *(const float4*)(B + (size_t)(k0 + kr) * N + n0 + bn4 * 4);
            Bs[kr][bn4 * 4 + 0] = f2tf(v.x);
            Bs[kr][bn4 * 4 + 1] = f2tf(v.y);
            Bs[kr][bn4 * 4 + 2] = f2tf(v.z);
            Bs[kr][bn4 * 4 + 3] = f2tf(v.w);
        }
        __syncthreads();

        #pragma unroll
        for (int ks = 0; ks < 4; ks++) {
            int kk = ks * 8;
            uint32_t af[4][4], bf[4][2];
            #pragma unroll
            for (int mt = 0; mt < 4; mt++) {
                int r = wm + mt * 16 + gr;
                af[mt][0] = As[r][kk + gc];
                af[mt][1] = As[r + 8][kk + gc];
                af[mt][2] = As[r][kk + 4 + gc];
                af[mt][3] = As[r + 8][kk + 4 + gc];
            }
            #pragma unroll
            for (int nt = 0; nt < 4; nt++) {
                int c = wn + nt * 8 + gr;
                bf[nt][0] = Bs[kk + gc][c];
                bf[nt][1] = Bs[kk + 4 + gc][c];
            }
            #pragma unroll
            for (int mt = 0; mt < 4; mt++)
                #pragma unroll
                for (int nt = 0; nt < 4; nt++)
                    mma_tf32(acc[mt][nt], af[mt], bf[nt]);
        }
        __syncthreads();
    }

    // epilogue
    #pragma unroll
    for (int mt = 0; mt < 4; mt++) {
        #pragma unroll
        for (int nt = 0; nt < 4; nt++) {
            int col = n0 + wn + nt * 8 + 2 * gc;
            float b0 = bias ? bias[col]     : 0.f;
            float b1 = bias ? bias[col + 1] : 0.f;
            #pragma unroll
            for (int h = 0; h < 2; h++) {
                int row = m0 + wm + mt * 16 + gr + h * 8;
                float c0 = acc[mt][nt][2 * h]     * alpha + b0;
                float c1 = acc[mt][nt][2 * h + 1] * alpha + b1;
                if (do_relu) { c0 = fmaxf(c0, 0.f); c1 = fmaxf(c1, 0.f); }
                if (Rz) {
                    const float2 r2 = *(const float2*)(Rz + (size_t)row * N + col);
                    c0 += r2.x; c1 += r2.y;
                }
                *(float2*)(C + (size_t)row * N + col) = make_float2(c0, c1);
            }
        }
    }
}

// ---------------- row softmax over N_SEQ, in place ----------------
__global__ void __launch_bounds__(256) softmax_kernel(float* __restrict__ sc) {
    size_t base = (size_t)blockIdx.x * N_SEQ;
    int t = threadIdx.x;
    float v[8];
    float mx = -1e30f;
    #pragma unroll
    for (int i = 0; i < 8; i++) {
        v[i] = sc[base + t + i * 256];
        mx = fmaxf(mx, v[i]);
    }
    __shared__ float red[8];
    int w = t >> 5, lane = t & 31;
    #pragma unroll
    for (int off = 16; off; off >>= 1)
        mx = fmaxf(mx, __shfl_xor_sync(0xffffffffu, mx, off));
    if (lane == 0) red[w] = mx;
    __syncthreads();
    if (t == 0) {
        float m = red[0];
        #pragma unroll
        for (int i = 1; i < 8; i++) m = fmaxf(m, red[i]);
        red[0] = m;
    }
    __syncthreads();
    mx = red[0];
    float s = 0.f;
    #pragma unroll
    for (int i = 0; i < 8; i++) { v[i] = __expf(v[i] - mx); s += v[i]; }
    #pragma unroll
    for (int off = 16; off; off >>= 1)
        s += __shfl_xor_sync(0xffffffffu, s, off);
    __syncthreads();
    if (lane == 0) red[w] = s;
    __syncthreads();
    if (t == 0) {
        float a = 0.f;
        #pragma unroll
        for (int i = 0; i < 8; i++) a += red[i];
        red[0] = 1.0f / a;
    }
    __syncthreads();
    float inv = red[0];
    #pragma unroll
    for (int i = 0; i < 8; i++) sc[base + t + i * 256] = v[i] * inv;
}

// ---------------- launch ----------------
extern "C" void kernel_launch(void* const* d_in, const int* in_sizes, int n_in,
                              void* d_out, int out_size) {
    const float* x   = (const float*)d_in[0];
    const float* w1  = (const float*)d_in[1];
    const float* b1  = (const float*)d_in[2];
    const float* w2  = (const float*)d_in[3];
    const float* b2  = (const float*)d_in[4];
    const float* g1  = (const float*)d_in[5];
    const float* be1 = (const float*)d_in[6];
    const float* g2  = (const float*)d_in[7];
    const float* be2 = (const float*)d_in[8];
    float* out = (float*)d_out;

    float *h, *hT, *x1, *h2, *mid, *sc;
    cudaGetSymbolAddress((void**)&h,   g_h);
    cudaGetSymbolAddress((void**)&hT,  g_hT);
    cudaGetSymbolAddress((void**)&x1,  g_x1);
    cudaGetSymbolAddress((void**)&h2,  g_h2);
    cudaGetSymbolAddress((void**)&mid, g_mid);
    cudaGetSymbolAddress((void**)&sc,  g_sc);

    const size_t sHD = (size_t)N_SEQ * D_DIM;     // 2048*256
    const size_t sS  = (size_t)N_SEQ * N_SEQ;     // 2048*2048

    // Sublayer 1
    ln_kernel<<<ROWS, 256>>>(x, g1, be1, h);
    transpose_kernel<<<dim3(N_SEQ / 32, D_DIM / 32, BATCH), 256>>>(h, hT);
    // S = (1/16) h @ hT   [batched 2048x2048x256]
    gemm_tf32<<<dim3(N_SEQ / 128, N_SEQ / 128, BATCH), 256>>>(
        h, hT, sc, nullptr, nullptr, N_SEQ, D_DIM, 0.0625f, 0, sHD, sHD, sS);
    softmax_kernel<<<ROWS, 256>>>(sc);
    // x1 = P @ h + x       [batched 2048x256x2048]
    gemm_tf32<<<dim3(N_SEQ / 128, D_DIM / 128, BATCH), 256>>>(
        sc, h, x1, nullptr, x, D_DIM, N_SEQ, 1.0f, 0, sS, sHD, sHD);

    // Sublayer 2
    ln_kernel<<<ROWS, 256>>>(x1, g2, be2, h2);
    // mid = relu(h2 @ w1 + b1)   [16384x1024x256]
    gemm_tf32<<<dim3(ROWS / 128, HID / 128, 1), 256>>>(
        h2, w1, mid, b1, nullptr, HID, D_DIM, 1.0f, 1, 0, 0, 0);
    // out = mid @ w2 + b2 + x1   [16384x256x1024]
    gemm_tf32<<<dim3(ROWS / 128, D_DIM / 128, 1), 256>>>(
        mid, w2, out, b2, x1, D_DIM, HID, 1.0f, 0, 0, 0, 0);
}

// round 3
// speedup vs baseline: 7.2308x; 1.0977x over previous
#include <cuda_runtime.h>
#include <math.h>
#include <stdint.h>

#define D_DIM 256
#define N_SEQ 2048
#define BATCH 8
#define ROWS (BATCH * N_SEQ)   // 16384
#define HID   1024

// ---------------- scratch ----------------
__device__ float g_h  [ROWS * D_DIM];   // LN1(x)
__device__ float g_x1 [ROWS * D_DIM];   // x + SA
__device__ float g_h2 [ROWS * D_DIM];   // LN2(x1)
__device__ float g_mid[ROWS * HID];     // relu(h2@w1+b1)

// ---------------- helpers ----------------
__device__ __forceinline__ void mma_tf32(float c[4], const uint32_t a[4], const uint32_t b[2]) {
    asm volatile("mma.sync.aligned.m16n8k8.row.col.f32.tf32.tf32.f32 "
                 "{%0,%1,%2,%3}, {%4,%5,%6,%7}, {%8,%9}, {%0,%1,%2,%3};"
                 : "+f"(c[0]), "+f"(c[1]), "+f"(c[2]), "+f"(c[3])
                 : "r"(a[0]), "r"(a[1]), "r"(a[2]), "r"(a[3]), "r"(b[0]), "r"(b[1]));
}

__device__ __forceinline__ void cpa16(uint32_t* dst_smem, const float* src) {
    uint32_t d = (uint32_t)__cvta_generic_to_shared(dst_smem);
    asm volatile("cp.async.cg.shared.global [%0], [%1], 16;\n" :: "r"(d), "l"(src));
}
__device__ __forceinline__ void cpa_commit() { asm volatile("cp.async.commit_group;\n"); }
template<int N> __device__ __forceinline__ void cpa_wait() {
    asm volatile("cp.async.wait_group %0;\n" :: "n"(N));
}

// ---------------- LayerNorm ----------------
__global__ void __launch_bounds__(256) ln_kernel(const float* __restrict__ x,
                                                 const float* __restrict__ gamma,
                                                 const float* __restrict__ beta,
                                                 float* __restrict__ out) {
    int row = blockIdx.x;
    int t = threadIdx.x;
    float v = x[(size_t)row * D_DIM + t];
    float s = v, s2 = v * v;
    #pragma unroll
    for (int off = 16; off; off >>= 1) {
        s  += __shfl_xor_sync(0xffffffffu, s,  off);
        s2 += __shfl_xor_sync(0xffffffffu, s2, off);
    }
    __shared__ float ws[8], ws2[8], mv[2];
    int w = t >> 5, lane = t & 31;
    if (lane == 0) { ws[w] = s; ws2[w] = s2; }
    __syncthreads();
    if (t == 0) {
        float a = 0.f, b = 0.f;
        #pragma unroll
        for (int i = 0; i < 8; i++) { a += ws[i]; b += ws2[i]; }
        float mean = a * (1.0f / D_DIM);
        float var  = b * (1.0f / D_DIM) - mean * mean;
        mv[0] = mean;
        mv[1] = rsqrtf(var + 1e-5f);
    }
    __syncthreads();
    out[(size_t)row * D_DIM + t] = (v - mv[0]) * mv[1] * gamma[t] + beta[t];
}

// ---------------- fused flash attention (tf32 HMMA) ----------------
// x1 = x + softmax(h h^T / 16) h    per batch.  Br=64 q-rows/CTA, Bc=64 keys/iter.
#define LDH 268   // 256 + 12 pad: (12*gr + gc) % 32 distinct -> conflict-free frags
#define LDP 76

#define QS_OFF   0
#define HS0_OFF  17152            // 64*268
#define HS1_OFF  34304
#define PS_OFF   51456            // + 64*268
#define SM_M     56320            // + 64*76
#define SM_L     56384
#define SM_AL    56448
#define SM_PMAX  56512
#define SM_PSUM  56640
#define ATTN_SMEM_WORDS 56768     // * 4 = 227072 bytes

__global__ void __launch_bounds__(256, 1) attn_kernel(const float* __restrict__ h,
                                                      const float* __restrict__ x,
                                                      float* __restrict__ x1) {
    extern __shared__ uint32_t sm[];
    float* smf = (float*)sm;

    int tid = threadIdx.x;
    int warp = tid >> 5, lane = tid & 31;
    int gr = lane >> 2, gc = lane & 3;
    int q0 = blockIdx.x * 64;
    const float* hb = h + (size_t)blockIdx.z * N_SEQ * D_DIM;

    if (tid < 64) { smf[SM_M + tid] = -1e30f; smf[SM_L + tid] = 0.f; }

    // prologue: Q tile + first H tile (group 0)
    {
        const float* qsrc = hb + (size_t)q0 * D_DIM;
        #pragma unroll
        for (int i = 0; i < 16; i++) {
            int c = tid + i * 256;
            int row = c >> 6, ch = c & 63;
            cpa16(&sm[QS_OFF + row * LDH + ch * 4], qsrc + row * 256 + ch * 4);
        }
        #pragma unroll
        for (int i = 0; i < 16; i++) {
            int c = tid + i * 256;
            int row = c >> 6, ch = c & 63;
            cpa16(&sm[HS0_OFF + row * LDH + ch * 4], hb + row * 256 + ch * 4);
        }
        cpa_commit();
    }

    float oacc[4][4][4];
    #pragma unroll
    for (int a = 0; a < 4; a++)
        #pragma unroll
        for (int b = 0; b < 4; b++)
            #pragma unroll
            for (int c = 0; c < 4; c++) oacc[a][b][c] = 0.f;

    int rb = warp >> 1, cb = warp & 1;

    for (int jt = 0; jt < N_SEQ / 64; jt++) {
        // prefetch next tile into other buffer
        if (jt + 1 < N_SEQ / 64) {
            uint32_t* dst = sm + (((jt + 1) & 1) ? HS1_OFF : HS0_OFF);
            const float* src = hb + (size_t)(jt + 1) * 64 * 256;
            #pragma unroll
            for (int i = 0; i < 16; i++) {
                int c = tid + i * 256;
                int row = c >> 6, ch = c & 63;
                cpa16(dst + row * LDH + ch * 4, src + row * 256 + ch * 4);
            }
            cpa_commit();
            cpa_wait<1>();
        } else {
            cpa_wait<0>();
        }
        __syncthreads();
        const uint32_t* HB = sm + ((jt & 1) ? HS1_OFF : HS0_OFF);

        // ---- S = Q @ H^T : warp tile 16x32 (rb row-block, cb col-block) ----
        float sacc[4][4];
        #pragma unroll
        for (int nt = 0; nt < 4; nt++)
            #pragma unroll
            for (int i = 0; i < 4; i++) sacc[nt][i] = 0.f;

        const uint32_t* Qr0 = sm + QS_OFF + (rb * 16 + gr) * LDH + gc;
        const uint32_t* Qr1 = Qr0 + 8 * LDH;
        #pragma unroll 4
        for (int ks = 0; ks < 32; ks++) {
            int kk = ks * 8;
            uint32_t a[4];
            a[0] = Qr0[kk]; a[1] = Qr1[kk]; a[2] = Qr0[kk + 4]; a[3] = Qr1[kk + 4];
            #pragma unroll
            for (int nt = 0; nt < 4; nt++) {
                const uint32_t* Hr = HB + (cb * 32 + nt * 8 + gr) * LDH + gc;
                uint32_t b[2] = { Hr[kk], Hr[kk + 4] };
                mma_tf32(sacc[nt], a, b);
            }
        }

        // ---- scale + row max (32-col partial per warp) ----
        float mx0 = -1e30f, mx1 = -1e30f;
        #pragma unroll
        for (int nt = 0; nt < 4; nt++) {
            #pragma unroll
            for (int i = 0; i < 4; i++) sacc[nt][i] *= 0.0625f;
            mx0 = fmaxf(mx0, fmaxf(sacc[nt][0], sacc[nt][1]));
            mx1 = fmaxf(mx1, fmaxf(sacc[nt][2], sacc[nt][3]));
        }
        mx0 = fmaxf(mx0, __shfl_xor_sync(0xffffffffu, mx0, 1));
        mx0 = fmaxf(mx0, __shfl_xor_sync(0xffffffffu, mx0, 2));
        mx1 = fmaxf(mx1, __shfl_xor_sync(0xffffffffu, mx1, 1));
        mx1 = fmaxf(mx1, __shfl_xor_sync(0xffffffffu, mx1, 2));
        if (gc == 0) {
            smf[SM_PMAX + cb * 64 + rb * 16 + gr]     = mx0;
            smf[SM_PMAX + cb * 64 + rb * 16 + 8 + gr] = mx1;
        }
        __syncthreads();
        if (tid < 64) {
            float mo = smf[SM_M + tid];
            float tm = fmaxf(smf[SM_PMAX + tid], smf[SM_PMAX + 64 + tid]);
            float mn = fmaxf(mo, tm);
            smf[SM_AL + tid] = __expf(mo - mn);
            smf[SM_M + tid] = mn;
        }
        __syncthreads();

        // ---- P = exp(S - m), write tile, partial row sums ----
        float mn0 = smf[SM_M + rb * 16 + gr];
        float mn1 = smf[SM_M + rb * 16 + 8 + gr];
        float s0 = 0.f, s1 = 0.f;
        #pragma unroll
        for (int nt = 0; nt < 4; nt++) {
            float p0 = __expf(sacc[nt][0] - mn0);
            float p1 = __expf(sacc[nt][1] - mn0);
            float p2 = __expf(sacc[nt][2] - mn1);
            float p3 = __expf(sacc[nt][3] - mn1);
            s0 += p0 + p1; s1 += p2 + p3;
            int col = cb * 32 + nt * 8 + 2 * gc;
            *(float2*)&smf[PS_OFF + (rb * 16 + gr) * LDP + col]     = make_float2(p0, p1);
            *(float2*)&smf[PS_OFF + (rb * 16 + 8 + gr) * LDP + col] = make_float2(p2, p3);
        }
        s0 += __shfl_xor_sync(0xffffffffu, s0, 1);
        s0 += __shfl_xor_sync(0xffffffffu, s0, 2);
        s1 += __shfl_xor_sync(0xffffffffu, s1, 1);
        s1 += __shfl_xor_sync(0xffffffffu, s1, 2);
        if (gc == 0) {
            smf[SM_PSUM + cb * 64 + rb * 16 + gr]     = s0;
            smf[SM_PSUM + cb * 64 + rb * 16 + 8 + gr] = s1;
        }
        __syncthreads();
        if (tid < 64)
            smf[SM_L + tid] = smf[SM_AL + tid] * smf[SM_L + tid]
                            + smf[SM_PSUM + tid] + smf[SM_PSUM + 64 + tid];

        // ---- rescale O by alpha ----
        #pragma unroll
        for (int mt = 0; mt < 4; mt++) {
            float al0 = smf[SM_AL + mt * 16 + gr];
            float al1 = smf[SM_AL + mt * 16 + 8 + gr];
            #pragma unroll
            for (int nt = 0; nt < 4; nt++) {
                oacc[mt][nt][0] *= al0; oacc[mt][nt][1] *= al0;
                oacc[mt][nt][2] *= al1; oacc[mt][nt][3] *= al1;
            }
        }

        // ---- O += P @ H : warp owns all 64 rows x 32 d-cols ----
        #pragma unroll
        for (int ks = 0; ks < 8; ks++) {
            int kk = ks * 8;
            uint32_t a[4][4];
            #pragma unroll
            for (int mt = 0; mt < 4; mt++) {
                const uint32_t* Pr0 = sm + PS_OFF + (mt * 16 + gr) * LDP + gc;
                const uint32_t* Pr1 = Pr0 + 8 * LDP;
                a[mt][0] = Pr0[kk]; a[mt][1] = Pr1[kk];
                a[mt][2] = Pr0[kk + 4]; a[mt][3] = Pr1[kk + 4];
            }
            #pragma unroll
            for (int nt = 0; nt < 4; nt++) {
                int col = warp * 32 + nt * 8 + gr;
                uint32_t b[2] = { HB[(kk + gc) * LDH + col], HB[(kk + 4 + gc) * LDH + col] };
                #pragma unroll
                for (int mt = 0; mt < 4; mt++)
                    mma_tf32(oacc[mt][nt], a[mt], b);
            }
        }
        __syncthreads();
    }

    // ---- epilogue: O/l + residual ----
    const float* xrow = x  + ((size_t)blockIdx.z * N_SEQ + q0) * D_DIM;
    float*       orow = x1 + ((size_t)blockIdx.z * N_SEQ + q0) * D_DIM;
    #pragma unroll
    for (int mt = 0; mt < 4; mt++) {
        float inv0 = 1.0f / smf[SM_L + mt * 16 + gr];
        float inv1 = 1.0f / smf[SM_L + mt * 16 + 8 + gr];
        #pragma unroll
        for (int nt = 0; nt < 4; nt++) {
            int col = warp * 32 + nt * 8 + 2 * gc;
            int r0 = mt * 16 + gr, r1 = r0 + 8;
            float2 xv0 = *(const float2*)&xrow[(size_t)r0 * D_DIM + col];
            float2 xv1 = *(const float2*)&xrow[(size_t)r1 * D_DIM + col];
            *(float2*)&orow[(size_t)r0 * D_DIM + col] =
                make_float2(oacc[mt][nt][0] * inv0 + xv0.x, oacc[mt][nt][1] * inv0 + xv0.y);
            *(float2*)&orow[(size_t)r1 * D_DIM + col] =
                make_float2(oacc[mt][nt][2] * inv1 + xv1.x, oacc[mt][nt][3] * inv1 + xv1.y);
        }
    }
}

// ---------------- tf32 NN GEMM, cp.async double-buffered ----------------
#define GLDA 36
#define GLDB 136
#define AS0_OFF 0
#define AS1_OFF 4608
#define BS0_OFF 9216
#define BS1_OFF 13568
#define GEMM_SMEM_WORDS 17920   // * 4 = 71680 bytes

__global__ void __launch_bounds__(256) gemm_tf32(const float* __restrict__ A,
                                                 const float* __restrict__ B,
                                                 float* __restrict__ C,
                                                 const float* __restrict__ bias,
                                                 const float* __restrict__ res,
                                                 int N, int K, int do_relu) {
    extern __shared__ uint32_t sm[];
    int tid = threadIdx.x;
    int warp = tid >> 5, lane = tid & 31;
    int m0 = blockIdx.x * 128, n0 = blockIdx.y * 128;
    int wm = (warp >> 2) * 64, wn = (warp & 3) * 32;
    int gr = lane >> 2, gc = lane & 3;

    float acc[4][4][4];
    #pragma unroll
    for (int i = 0; i < 4; i++)
        #pragma unroll
        for (int j = 0; j < 4; j++)
            #pragma unroll
            for (int v = 0; v < 4; v++) acc[i][j][v] = 0.f;

    int fa_row = tid >> 3, fa_ch = tid & 7;     // A: 128 rows x 8 chunks, tid-major rowpacks
    int fb_row = tid >> 5, fb_ch = tid & 31;    // B: 32 rows x 32 chunks

    // prologue: k-tile 0 -> buf0
    {
        const float* Ap = A + (size_t)m0 * K;
        const float* Bp = B + n0;
        #pragma unroll
        for (int i = 0; i < 4; i++) {
            int c = tid + i * 256;
            int row = c >> 3, ch = c & 7;
            cpa16(sm + AS0_OFF + row * GLDA + ch * 4, Ap + (size_t)row * K + ch * 4);
        }
        #pragma unroll
        for (int i = 0; i < 4; i++) {
            int c = tid + i * 256;
            int row = c >> 5, ch = c & 31;
            cpa16(sm + BS0_OFF + row * GLDB + ch * 4, Bp + (size_t)row * N + ch * 4);
        }
        cpa_commit();
    }

    int ntiles = K >> 5;
    for (int kt = 0; kt < ntiles; kt++) {
        if (kt + 1 < ntiles) {
            int k0 = (kt + 1) * 32;
            uint32_t* as = sm + (((kt + 1) & 1) ? AS1_OFF : AS0_OFF);
            uint32_t* bs = sm + (((kt + 1) & 1) ? BS1_OFF : BS0_OFF);
            const float* Ap = A + (size_t)m0 * K + k0;
            const float* Bp = B + (size_t)k0 * N + n0;
            #pragma unroll
            for (int i = 0; i < 4; i++) {
                int c = tid + i * 256;
                int row = c >> 3, ch = c & 7;
                cpa16(as + row * GLDA + ch * 4, Ap + (size_t)row * K + ch * 4);
            }
            #pragma unroll
            for (int i = 0; i < 4; i++) {
                int c = tid + i * 256;
                int row = c >> 5, ch = c & 31;
                cpa16(bs + row * GLDB + ch * 4, Bp + (size_t)row * N + ch * 4);
            }
            cpa_commit();
            cpa_wait<1>();
        } else {
            cpa_wait<0>();
        }
        __syncthreads();

        const uint32_t* AS = sm + ((kt & 1) ? AS1_OFF : AS0_OFF);
        const uint32_t* BS = sm + ((kt & 1) ? BS1_OFF : BS0_OFF);

        #pragma unroll
        for (int ks = 0; ks < 4; ks++) {
            int kk = ks * 8;
            uint32_t af[4][4], bf[4][2];
            #pragma unroll
            for (int mt = 0; mt < 4; mt++) {
                const uint32_t* Ar0 = AS + (wm + mt * 16 + gr) * GLDA + gc;
                const uint32_t* Ar1 = Ar0 + 8 * GLDA;
                af[mt][0] = Ar0[kk]; af[mt][1] = Ar1[kk];
                af[mt][2] = Ar0[kk + 4]; af[mt][3] = Ar1[kk + 4];
            }
            #pragma unroll
            for (int nt = 0; nt < 4; nt++) {
                int c = wn + nt * 8 + gr;
                bf[nt][0] = BS[(kk + gc) * GLDB + c];
                bf[nt][1] = BS[(kk + 4 + gc) * GLDB + c];
            }
            #pragma unroll
            for (int mt = 0; mt < 4; mt++)
                #pragma unroll
                for (int nt = 0; nt < 4; nt++)
                    mma_tf32(acc[mt][nt], af[mt], bf[nt]);
        }
        __syncthreads();
    }

    #pragma unroll
    for (int mt = 0; mt < 4; mt++) {
        #pragma unroll
        for (int nt = 0; nt < 4; nt++) {
            int col = n0 + wn + nt * 8 + 2 * gc;
            float b0 = bias[col], b1 = bias[col + 1];
            #pragma unroll
            for (int hh = 0; hh < 2; hh++) {
                int row = m0 + wm + mt * 16 + gr + hh * 8;
                float c0 = acc[mt][nt][2 * hh]     + b0;
                float c1 = acc[mt][nt][2 * hh + 1] + b1;
                if (do_relu) { c0 = fmaxf(c0, 0.f); c1 = fmaxf(c1, 0.f); }
                if (res) {
                    float2 r2 = *(const float2*)(res + (size_t)row * N + col);
                    c0 += r2.x; c1 += r2.y;
                }
                *(float2*)(C + (size_t)row * N + col) = make_float2(c0, c1);
            }
        }
    }
}

// ---------------- launch ----------------
extern "C" void kernel_launch(void* const* d_in, const int* in_sizes, int n_in,
                              void* d_out, int out_size) {
    const float* x   = (const float*)d_in[0];
    const float* w1  = (const float*)d_in[1];
    const float* b1  = (const float*)d_in[2];
    const float* w2  = (const float*)d_in[3];
    const float* b2  = (const float*)d_in[4];
    const float* g1  = (const float*)d_in[5];
    const float* be1 = (const float*)d_in[6];
    const float* g2  = (const float*)d_in[7];
    const float* be2 = (const float*)d_in[8];
    float* out = (float*)d_out;

    float *h, *x1, *h2, *mid;
    cudaGetSymbolAddress((void**)&h,   g_h);
    cudaGetSymbolAddress((void**)&x1,  g_x1);
    cudaGetSymbolAddress((void**)&h2,  g_h2);
    cudaGetSymbolAddress((void**)&mid, g_mid);

    static int attr_done = 0;
    if (!attr_done) {
        cudaFuncSetAttribute(attn_kernel, cudaFuncAttributeMaxDynamicSharedMemorySize,
                             ATTN_SMEM_WORDS * 4);
        cudaFuncSetAttribute(gemm_tf32, cudaFuncAttributeMaxDynamicSharedMemorySize,
                             GEMM_SMEM_WORDS * 4);
        attr_done = 1;
    }

    // Sublayer 1: fused flash attention
    ln_kernel<<<ROWS, 256>>>(x, g1, be1, h);
    attn_kernel<<<dim3(N_SEQ / 64, 1, BATCH), 256, ATTN_SMEM_WORDS * 4>>>(h, x, x1);

    // Sublayer 2: FFN
    ln_kernel<<<ROWS, 256>>>(x1, g2, be2, h2);
    gemm_tf32<<<dim3(ROWS / 128, HID / 128), 256, GEMM_SMEM_WORDS * 4>>>(
        h2, w1, mid, b1, nullptr, HID, D_DIM, 1);
    gemm_tf32<<<dim3(ROWS / 128, D_DIM / 128), 256, GEMM_SMEM_WORDS * 4>>>(
        mid, w2, out, b2, x1, D_DIM, HID, 0);
}

// round 4
// speedup vs baseline: 12.3954x; 1.7143x over previous
#include <cuda_runtime.h>
#include <cuda_fp16.h>
#include <math.h>
#include <stdint.h>

#define D_DIM 256
#define N_SEQ 2048
#define BATCH 8
#define ROWS (BATCH * N_SEQ)   // 16384
#define HID   1024

// ---------------- scratch ----------------
__device__ __half g_hh [ROWS * D_DIM];   // LN1(x) fp16
__device__ float  g_x1 [ROWS * D_DIM];   // x + SA  fp32
__device__ __half g_h2h[ROWS * D_DIM];   // LN2(x1) fp16
__device__ __half g_mid[ROWS * HID];     // relu(...) fp16
__device__ __half g_w1T[HID * D_DIM];    // w1^T fp16  [N=1024][K=256]
__device__ __half g_w2T[D_DIM * HID];    // w2^T fp16  [N=256][K=1024]

// ---------------- helpers ----------------
__device__ __forceinline__ void mma_f16(float c[4], const uint32_t a[4], const uint32_t b[2]) {
    asm volatile("mma.sync.aligned.m16n8k16.row.col.f32.f16.f16.f32 "
                 "{%0,%1,%2,%3}, {%4,%5,%6,%7}, {%8,%9}, {%0,%1,%2,%3};"
                 : "+f"(c[0]), "+f"(c[1]), "+f"(c[2]), "+f"(c[3])
                 : "r"(a[0]), "r"(a[1]), "r"(a[2]), "r"(a[3]), "r"(b[0]), "r"(b[1]));
}

__device__ __forceinline__ void cpa16(const __half* dst_smem, const __half* src) {
    uint32_t d = (uint32_t)__cvta_generic_to_shared(dst_smem);
    asm volatile("cp.async.cg.shared.global [%0], [%1], 16;\n" :: "r"(d), "l"(src));
}
__device__ __forceinline__ void cpa_commit() { asm volatile("cp.async.commit_group;\n"); }
template<int N> __device__ __forceinline__ void cpa_wait() {
    asm volatile("cp.async.wait_group %0;\n" :: "n"(N));
}
__device__ __forceinline__ uint32_t ldu32(const __half* p) { return *(const uint32_t*)p; }

// ---------------- LayerNorm (fp32 in, fp16 out) ----------------
__global__ void __launch_bounds__(256) ln_kernel(const float* __restrict__ x,
                                                 const float* __restrict__ gamma,
                                                 const float* __restrict__ beta,
                                                 __half* __restrict__ out) {
    int row = blockIdx.x;
    int t = threadIdx.x;
    float v = x[(size_t)row * D_DIM + t];
    float s = v, s2 = v * v;
    #pragma unroll
    for (int off = 16; off; off >>= 1) {
        s  += __shfl_xor_sync(0xffffffffu, s,  off);
        s2 += __shfl_xor_sync(0xffffffffu, s2, off);
    }
    __shared__ float ws[8], ws2[8], mv[2];
    int w = t >> 5, lane = t & 31;
    if (lane == 0) { ws[w] = s; ws2[w] = s2; }
    __syncthreads();
    if (t == 0) {
        float a = 0.f, b = 0.f;
        #pragma unroll
        for (int i = 0; i < 8; i++) { a += ws[i]; b += ws2[i]; }
        float mean = a * (1.0f / D_DIM);
        float var  = b * (1.0f / D_DIM) - mean * mean;
        mv[0] = mean;
        mv[1] = rsqrtf(var + 1e-5f);
    }
    __syncthreads();
    out[(size_t)row * D_DIM + t] = __float2half((v - mv[0]) * mv[1] * gamma[t] + beta[t]);
}

// ---------------- weight transpose + fp16 convert: w[K][N] -> wT[N][K] ----------------
__global__ void __launch_bounds__(256) wt_kernel(const float* __restrict__ w,
                                                 __half* __restrict__ wT, int K, int N) {
    __shared__ float t[32][33];
    int n0 = blockIdx.x * 32, k0 = blockIdx.y * 32;
    int tx = threadIdx.x & 31, ty = threadIdx.x >> 5;   // 32 x 8
    #pragma unroll
    for (int j = 0; j < 4; j++)
        t[ty + j * 8][tx] = w[(size_t)(k0 + ty + j * 8) * N + n0 + tx];
    __syncthreads();
    #pragma unroll
    for (int j = 0; j < 4; j++)
        wT[(size_t)(n0 + ty + j * 8) * K + k0 + tx] = __float2half(t[tx][ty + j * 8]);
}

// ---------------- fused flash attention, fp16 HMMA ----------------
// Br=64 q-rows/CTA, Bc=64 keys/iter.  All offsets in HALF units.
#define LDQ 264   // 256 + 8 pad (row pitch 528B; 528%128=16 -> conflict-free)
#define LDP 72

#define QS  0
#define HS0 16896            // 64*264
#define HS1 33792
#define PS  50688            // + 64*264
#define HALF_WORDS 55296     // + 64*72  -> bytes: 110592
#define FM    0
#define FL    64
#define FAL   128
#define FPMAX 192
#define FPSUM 320
#define ATTN_SMEM_BYTES (110592 + 448 * 4)   // 112384 -> 2 CTAs/SM

__global__ void __launch_bounds__(256, 2) attn_kernel(const __half* __restrict__ h,
                                                      const float* __restrict__ x,
                                                      float* __restrict__ x1) {
    extern __shared__ __half sh[];
    float* smf = (float*)(sh + HALF_WORDS);

    int tid = threadIdx.x;
    int warp = tid >> 5, lane = tid & 31;
    int gr = lane >> 2, gc = lane & 3;
    int rb = warp >> 1, cb = warp & 1;
    int q0 = blockIdx.x * 64;
    const __half* hb = h + (size_t)blockIdx.z * N_SEQ * D_DIM;

    if (tid < 64) { smf[FM + tid] = -1e30f; smf[FL + tid] = 0.f; }

    // prologue: Q tile + H tile 0
    {
        const __half* qsrc = hb + (size_t)q0 * D_DIM;
        #pragma unroll
        for (int i = 0; i < 8; i++) {
            int c = tid + i * 256;
            int row = c >> 5, ch = c & 31;
            cpa16(sh + QS + row * LDQ + ch * 8, qsrc + (size_t)row * D_DIM + ch * 8);
        }
        #pragma unroll
        for (int i = 0; i < 8; i++) {
            int c = tid + i * 256;
            int row = c >> 5, ch = c & 31;
            cpa16(sh + HS0 + row * LDQ + ch * 8, hb + (size_t)row * D_DIM + ch * 8);
        }
        cpa_commit();
    }

    float oacc[4][4][4];
    #pragma unroll
    for (int a = 0; a < 4; a++)
        #pragma unroll
        for (int b = 0; b < 4; b++)
            #pragma unroll
            for (int c = 0; c < 4; c++) oacc[a][b][c] = 0.f;

    for (int jt = 0; jt < N_SEQ / 64; jt++) {
        if (jt + 1 < N_SEQ / 64) {
            __half* dst = sh + (((jt + 1) & 1) ? HS1 : HS0);
            const __half* src = hb + (size_t)(jt + 1) * 64 * D_DIM;
            #pragma unroll
            for (int i = 0; i < 8; i++) {
                int c = tid + i * 256;
                int row = c >> 5, ch = c & 31;
                cpa16(dst + row * LDQ + ch * 8, src + (size_t)row * D_DIM + ch * 8);
            }
            cpa_commit();
            cpa_wait<1>();
        } else {
            cpa_wait<0>();
        }
        __syncthreads();
        const __half* HB = sh + ((jt & 1) ? HS1 : HS0);

        // ---- S = Q @ H^T (warp tile 16x32) ----
        float sacc[4][4];
        #pragma unroll
        for (int nt = 0; nt < 4; nt++)
            #pragma unroll
            for (int i = 0; i < 4; i++) sacc[nt][i] = 0.f;

        const __half* Qb = sh + QS + (rb * 16 + gr) * LDQ + 2 * gc;
        #pragma unroll
        for (int ks = 0; ks < 16; ks++) {
            int kk = ks * 16;
            uint32_t a[4];
            a[0] = ldu32(Qb + kk);
            a[1] = ldu32(Qb + 8 * LDQ + kk);
            a[2] = ldu32(Qb + kk + 8);
            a[3] = ldu32(Qb + 8 * LDQ + kk + 8);
            #pragma unroll
            for (int nt = 0; nt < 4; nt++) {
                const __half* Hr = HB + (cb * 32 + nt * 8 + gr) * LDQ + kk + 2 * gc;
                uint32_t b[2] = { ldu32(Hr), ldu32(Hr + 8) };
                mma_f16(sacc[nt], a, b);
            }
        }

        // ---- scale + row max ----
        float mx0 = -1e30f, mx1 = -1e30f;
        #pragma unroll
        for (int nt = 0; nt < 4; nt++) {
            #pragma unroll
            for (int i = 0; i < 4; i++) sacc[nt][i] *= 0.0625f;
            mx0 = fmaxf(mx0, fmaxf(sacc[nt][0], sacc[nt][1]));
            mx1 = fmaxf(mx1, fmaxf(sacc[nt][2], sacc[nt][3]));
        }
        mx0 = fmaxf(mx0, __shfl_xor_sync(0xffffffffu, mx0, 1));
        mx0 = fmaxf(mx0, __shfl_xor_sync(0xffffffffu, mx0, 2));
        mx1 = fmaxf(mx1, __shfl_xor_sync(0xffffffffu, mx1, 1));
        mx1 = fmaxf(mx1, __shfl_xor_sync(0xffffffffu, mx1, 2));
        if (gc == 0) {
            smf[FPMAX + cb * 64 + rb * 16 + gr]     = mx0;
            smf[FPMAX + cb * 64 + rb * 16 + 8 + gr] = mx1;
        }
        __syncthreads();
        if (tid < 64) {
            float mo = smf[FM + tid];
            float tm = fmaxf(smf[FPMAX + tid], smf[FPMAX + 64 + tid]);
            float mn = fmaxf(mo, tm);
            smf[FAL + tid] = __expf(mo - mn);
            smf[FM + tid] = mn;
        }
        __syncthreads();

        // ---- P = exp(S - m) -> half2 tile + partial sums ----
        float mn0 = smf[FM + rb * 16 + gr];
        float mn1 = smf[FM + rb * 16 + 8 + gr];
        float s0 = 0.f, s1 = 0.f;
        #pragma unroll
        for (int nt = 0; nt < 4; nt++) {
            float p0 = __expf(sacc[nt][0] - mn0);
            float p1 = __expf(sacc[nt][1] - mn0);
            float p2 = __expf(sacc[nt][2] - mn1);
            float p3 = __expf(sacc[nt][3] - mn1);
            s0 += p0 + p1; s1 += p2 + p3;
            int col = cb * 32 + nt * 8 + 2 * gc;
            *(__half2*)(sh + PS + (rb * 16 + gr) * LDP + col)     = __floats2half2_rn(p0, p1);
            *(__half2*)(sh + PS + (rb * 16 + 8 + gr) * LDP + col) = __floats2half2_rn(p2, p3);
        }
        s0 += __shfl_xor_sync(0xffffffffu, s0, 1);
        s0 += __shfl_xor_sync(0xffffffffu, s0, 2);
        s1 += __shfl_xor_sync(0xffffffffu, s1, 1);
        s1 += __shfl_xor_sync(0xffffffffu, s1, 2);
        if (gc == 0) {
            smf[FPSUM + cb * 64 + rb * 16 + gr]     = s0;
            smf[FPSUM + cb * 64 + rb * 16 + 8 + gr] = s1;
        }
        __syncthreads();
        if (tid < 64)
            smf[FL + tid] = smf[FAL + tid] * smf[FL + tid]
                          + smf[FPSUM + tid] + smf[FPSUM + 64 + tid];

        // ---- rescale O ----
        #pragma unroll
        for (int mt = 0; mt < 4; mt++) {
            float al0 = smf[FAL + mt * 16 + gr];
            float al1 = smf[FAL + mt * 16 + 8 + gr];
            #pragma unroll
            for (int nt = 0; nt < 4; nt++) {
                oacc[mt][nt][0] *= al0; oacc[mt][nt][1] *= al0;
                oacc[mt][nt][2] *= al1; oacc[mt][nt][3] *= al1;
            }
        }

        // ---- O += P @ H (warp: 64 rows x 32 d-cols) ----
        #pragma unroll
        for (int ks = 0; ks < 4; ks++) {
            int kk = ks * 16;
            uint32_t a[4][4];
            #pragma unroll
            for (int mt = 0; mt < 4; mt++) {
                const __half* Pr = sh + PS + (mt * 16 + gr) * LDP + kk + 2 * gc;
                a[mt][0] = ldu32(Pr);
                a[mt][1] = ldu32(Pr + 8 * LDP);
                a[mt][2] = ldu32(Pr + 8);
                a[mt][3] = ldu32(Pr + 8 * LDP + 8);
            }
            #pragma unroll
            for (int nt = 0; nt < 4; nt++) {
                int col = warp * 32 + nt * 8 + gr;
                const __half* Hc = HB + col;
                uint32_t lo0 = *(const unsigned short*)(Hc + (kk + 2 * gc) * LDQ);
                uint32_t hi0 = *(const unsigned short*)(Hc + (kk + 2 * gc + 1) * LDQ);
                uint32_t lo1 = *(const unsigned short*)(Hc + (kk + 2 * gc + 8) * LDQ);
                uint32_t hi1 = *(const unsigned short*)(Hc + (kk + 2 * gc + 9) * LDQ);
                uint32_t b[2] = { __byte_perm(lo0, hi0, 0x5410), __byte_perm(lo1, hi1, 0x5410) };
                #pragma unroll
                for (int mt = 0; mt < 4; mt++)
                    mma_f16(oacc[mt][nt], a[mt], b);
            }
        }
        __syncthreads();
    }

    // ---- epilogue ----
    const float* xrow = x  + ((size_t)blockIdx.z * N_SEQ + q0) * D_DIM;
    float*       orow = x1 + ((size_t)blockIdx.z * N_SEQ + q0) * D_DIM;
    #pragma unroll
    for (int mt = 0; mt < 4; mt++) {
        float inv0 = 1.0f / smf[FL + mt * 16 + gr];
        float inv1 = 1.0f / smf[FL + mt * 16 + 8 + gr];
        #pragma unroll
        for (int nt = 0; nt < 4; nt++) {
            int col = warp * 32 + nt * 8 + 2 * gc;
            int r0 = mt * 16 + gr, r1 = r0 + 8;
            float2 xv0 = *(const float2*)&xrow[(size_t)r0 * D_DIM + col];
            float2 xv1 = *(const float2*)&xrow[(size_t)r1 * D_DIM + col];
            *(float2*)&orow[(size_t)r0 * D_DIM + col] =
                make_float2(oacc[mt][nt][0] * inv0 + xv0.x, oacc[mt][nt][1] * inv0 + xv0.y);
            *(float2*)&orow[(size_t)r1 * D_DIM + col] =
                make_float2(oacc[mt][nt][2] * inv1 + xv1.x, oacc[mt][nt][3] * inv1 + xv1.y);
        }
    }
}

// ---------------- fp16 GEMM: C[M,N] = A[M,K] @ Bt[N,K]^T  (cp.async 2-stage) ----------------
#define GP 72      // halves per smem row (144B; conflict-free (4gr+gc))
#define GAS0 0
#define GBS0 9216
#define GAS1 18432
#define GBS1 27648
#define GEMM_SMEM_BYTES (36864 * 2)   // 73728

__global__ void __launch_bounds__(256, 2) gemm_f16(const __half* __restrict__ A,
                                                   const __half* __restrict__ Bt,
                                                   void* __restrict__ Cv,
                                                   const float* __restrict__ bias,
                                                   const float* __restrict__ res,
                                                   int N, int K, int do_relu, int out_half) {
    extern __shared__ __half sh[];
    int tid = threadIdx.x;
    int warp = tid >> 5, lane = tid & 31;
    int m0 = blockIdx.x * 128, n0 = blockIdx.y * 128;
    int wm = (warp >> 2) * 64, wn = (warp & 3) * 32;
    int gr = lane >> 2, gc = lane & 3;

    float acc[4][4][4];
    #pragma unroll
    for (int i = 0; i < 4; i++)
        #pragma unroll
        for (int j = 0; j < 4; j++)
            #pragma unroll
            for (int v = 0; v < 4; v++) acc[i][j][v] = 0.f;

    // prologue: k-tile 0
    {
        #pragma unroll
        for (int i = 0; i < 4; i++) {
            int c = tid + i * 256;
            int row = c >> 3, ch = c & 7;
            cpa16(sh + GAS0 + row * GP + ch * 8, A + (size_t)(m0 + row) * K + ch * 8);
        }
        #pragma unroll
        for (int i = 0; i < 4; i++) {
            int c = tid + i * 256;
            int row = c >> 3, ch = c & 7;
            cpa16(sh + GBS0 + row * GP + ch * 8, Bt + (size_t)(n0 + row) * K + ch * 8);
        }
        cpa_commit();
    }

    int ntiles = K >> 6;
    for (int kt = 0; kt < ntiles; kt++) {
        if (kt + 1 < ntiles) {
            int k0 = (kt + 1) * 64;
            __half* as = sh + (((kt + 1) & 1) ? GAS1 : GAS0);
            __half* bs = sh + (((kt + 1) & 1) ? GBS1 : GBS0);
            #pragma unroll
            for (int i = 0; i < 4; i++) {
                int c = tid + i * 256;
                int row = c >> 3, ch = c & 7;
                cpa16(as + row * GP + ch * 8, A + (size_t)(m0 + row) * K + k0 + ch * 8);
            }
            #pragma unroll
            for (int i = 0; i < 4; i++) {
                int c = tid + i * 256;
                int row = c >> 3, ch = c & 7;
                cpa16(bs + row * GP + ch * 8, Bt + (size_t)(n0 + row) * K + k0 + ch * 8);
            }
            cpa_commit();
            cpa_wait<1>();
        } else {
            cpa_wait<0>();
        }
        __syncthreads();

        const __half* AS = sh + ((kt & 1) ? GAS1 : GAS0);
        const __half* BS = sh + ((kt & 1) ? GBS1 : GBS0);

        #pragma unroll
        for (int ks = 0; ks < 4; ks++) {
            int kk = ks * 16;
            uint32_t af[4][4], bf[4][2];
            #pragma unroll
            for (int mt = 0; mt < 4; mt++) {
                const __half* Ar = AS + (wm + mt * 16 + gr) * GP + kk + 2 * gc;
                af[mt][0] = ldu32(Ar);
                af[mt][1] = ldu32(Ar + 8 * GP);
                af[mt][2] = ldu32(Ar + 8);
                af[mt][3] = ldu32(Ar + 8 * GP + 8);
            }
            #pragma unroll
            for (int nt = 0; nt < 4; nt++) {
                const __half* Br = BS + (wn + nt * 8 + gr) * GP + kk + 2 * gc;
                bf[nt][0] = ldu32(Br);
                bf[nt][1] = ldu32(Br + 8);
            }
            #pragma unroll
            for (int mt = 0; mt < 4; mt++)
                #pragma unroll
                for (int nt = 0; nt < 4; nt++)
                    mma_f16(acc[mt][nt], af[mt], bf[nt]);
        }
        __syncthreads();
    }

    #pragma unroll
    for (int mt = 0; mt < 4; mt++) {
        #pragma unroll
        for (int nt = 0; nt < 4; nt++) {
            int col = n0 + wn + nt * 8 + 2 * gc;
            float b0 = bias[col], b1 = bias[col + 1];
            #pragma unroll
            for (int hh = 0; hh < 2; hh++) {
                int row = m0 + wm + mt * 16 + gr + hh * 8;
                float c0 = acc[mt][nt][2 * hh]     + b0;
                float c1 = acc[mt][nt][2 * hh + 1] + b1;
                if (do_relu) { c0 = fmaxf(c0, 0.f); c1 = fmaxf(c1, 0.f); }
                if (res) {
                    float2 r2 = *(const float2*)(res + (size_t)row * N + col);
                    c0 += r2.x; c1 += r2.y;
                }
                if (out_half) {
                    *(__half2*)((__half*)Cv + (size_t)row * N + col) = __floats2half2_rn(c0, c1);
                } else {
                    *(float2*)((float*)Cv + (size_t)row * N + col) = make_float2(c0, c1);
                }
            }
        }
    }
}

// ---------------- launch ----------------
extern "C" void kernel_launch(void* const* d_in, const int* in_sizes, int n_in,
                              void* d_out, int out_size) {
    const float* x   = (const float*)d_in[0];
    const float* w1  = (const float*)d_in[1];
    const float* b1  = (const float*)d_in[2];
    const float* w2  = (const float*)d_in[3];
    const float* b2  = (const float*)d_in[4];
    const float* g1  = (const float*)d_in[5];
    const float* be1 = (const float*)d_in[6];
    const float* g2  = (const float*)d_in[7];
    const float* be2 = (const float*)d_in[8];
    float* out = (float*)d_out;

    __half *hh, *h2h, *mid, *w1T, *w2T;
    float *x1;
    cudaGetSymbolAddress((void**)&hh,  g_hh);
    cudaGetSymbolAddress((void**)&x1,  g_x1);
    cudaGetSymbolAddress((void**)&h2h, g_h2h);
    cudaGetSymbolAddress((void**)&mid, g_mid);
    cudaGetSymbolAddress((void**)&w1T, g_w1T);
    cudaGetSymbolAddress((void**)&w2T, g_w2T);

    cudaFuncSetAttribute(attn_kernel, cudaFuncAttributeMaxDynamicSharedMemorySize,
                         ATTN_SMEM_BYTES);
    cudaFuncSetAttribute(gemm_f16, cudaFuncAttributeMaxDynamicSharedMemorySize,
                         GEMM_SMEM_BYTES);

    // weight prep (fp16 transposed copies)
    wt_kernel<<<dim3(HID / 32, D_DIM / 32), 256>>>(w1, w1T, D_DIM, HID);
    wt_kernel<<<dim3(D_DIM / 32, HID / 32), 256>>>(w2, w2T, HID, D_DIM);

    // Sublayer 1
    ln_kernel<<<ROWS, 256>>>(x, g1, be1, hh);
    attn_kernel<<<dim3(N_SEQ / 64, 1, BATCH), 256, ATTN_SMEM_BYTES>>>(hh, x, x1);

    // Sublayer 2
    ln_kernel<<<ROWS, 256>>>(x1, g2, be2, h2h);
    gemm_f16<<<dim3(ROWS / 128, HID / 128), 256, GEMM_SMEM_BYTES>>>(
        h2h, w1T, mid, b1, nullptr, HID, D_DIM, 1, 1);
    gemm_f16<<<dim3(ROWS / 128, D_DIM / 128), 256, GEMM_SMEM_BYTES>>>(
        mid, w2T, out, b2, x1, D_DIM, HID, 0, 0);
}

// round 6
// speedup vs baseline: 14.1574x; 1.1422x over previous
#include <cuda_runtime.h>
#include <cuda_fp16.h>
#include <math.h>
#include <stdint.h>

#define D_DIM 256
#define N_SEQ 2048
#define BATCH 8
#define ROWS (BATCH * N_SEQ)   // 16384
#define HID   1024

// ---------------- scratch ----------------
__device__ __half g_hh [ROWS * D_DIM];   // LN1(x) fp16
__device__ float  g_x1 [ROWS * D_DIM];   // x + SA  fp32
__device__ __half g_h2h[ROWS * D_DIM];   // LN2(x1) fp16
__device__ __half g_mid[ROWS * HID];     // relu(...) fp16
__device__ __half g_w1T[HID * D_DIM];    // w1^T fp16
__device__ __half g_w2T[D_DIM * HID];    // w2^T fp16

// ---------------- helpers ----------------
__device__ __forceinline__ void mma_f16(float c[4], const uint32_t a[4], const uint32_t b[2]) {
    asm volatile("mma.sync.aligned.m16n8k16.row.col.f32.f16.f16.f32 "
                 "{%0,%1,%2,%3}, {%4,%5,%6,%7}, {%8,%9}, {%0,%1,%2,%3};"
                 : "+f"(c[0]), "+f"(c[1]), "+f"(c[2]), "+f"(c[3])
                 : "r"(a[0]), "r"(a[1]), "r"(a[2]), "r"(a[3]), "r"(b[0]), "r"(b[1]));
}
__device__ __forceinline__ uint32_t pack_f16x2(float lo, float hi) {
    uint32_t r;
    asm("cvt.rn.f16x2.f32 %0, %1, %2;" : "=r"(r) : "f"(hi), "f"(lo));
    return r;
}
__device__ __forceinline__ void ldsm4(uint32_t r[4], uint32_t addr) {
    asm volatile("ldmatrix.sync.aligned.m8n8.x4.shared.b16 {%0,%1,%2,%3}, [%4];"
                 : "=r"(r[0]), "=r"(r[1]), "=r"(r[2]), "=r"(r[3]) : "r"(addr));
}
__device__ __forceinline__ void ldsm4t(uint32_t r[4], uint32_t addr) {
    asm volatile("ldmatrix.sync.aligned.m8n8.x4.trans.shared.b16 {%0,%1,%2,%3}, [%4];"
                 : "=r"(r[0]), "=r"(r[1]), "=r"(r[2]), "=r"(r[3]) : "r"(addr));
}
__device__ __forceinline__ void cpa16(const __half* dst_smem, const __half* src) {
    uint32_t d = (uint32_t)__cvta_generic_to_shared(dst_smem);
    asm volatile("cp.async.cg.shared.global [%0], [%1], 16;\n" :: "r"(d), "l"(src));
}
__device__ __forceinline__ void cpa_commit() { asm volatile("cp.async.commit_group;\n"); }
template<int N> __device__ __forceinline__ void cpa_wait() {
    asm volatile("cp.async.wait_group %0;\n" :: "n"(N));
}
__device__ __forceinline__ uint32_t ldu32(const __half* p) { return *(const uint32_t*)p; }

// ---------------- LayerNorm (fp32 in, fp16 out) ----------------
__global__ void __launch_bounds__(256) ln_kernel(const float* __restrict__ x,
                                                 const float* __restrict__ gamma,
                                                 const float* __restrict__ beta,
                                                 __half* __restrict__ out) {
    int row = blockIdx.x;
    int t = threadIdx.x;
    float v = x[(size_t)row * D_DIM + t];
    float s = v, s2 = v * v;
    #pragma unroll
    for (int off = 16; off; off >>= 1) {
        s  += __shfl_xor_sync(0xffffffffu, s,  off);
        s2 += __shfl_xor_sync(0xffffffffu, s2, off);
    }
    __shared__ float ws[8], ws2[8], mv[2];
    int w = t >> 5, lane = t & 31;
    if (lane == 0) { ws[w] = s; ws2[w] = s2; }
    __syncthreads();
    if (t == 0) {
        float a = 0.f, b = 0.f;
        #pragma unroll
        for (int i = 0; i < 8; i++) { a += ws[i]; b += ws2[i]; }
        float mean = a * (1.0f / D_DIM);
        float var  = b * (1.0f / D_DIM) - mean * mean;
        mv[0] = mean;
        mv[1] = rsqrtf(var + 1e-5f);
    }
    __syncthreads();
    out[(size_t)row * D_DIM + t] = __float2half((v - mv[0]) * mv[1] * gamma[t] + beta[t]);
}

// ---------------- weight transpose + fp16: w[K][N] -> wT[N][K] ----------------
__global__ void __launch_bounds__(256) wt_kernel(const float* __restrict__ w,
                                                 __half* __restrict__ wT, int K, int N) {
    __shared__ float t[32][33];
    int n0 = blockIdx.x * 32, k0 = blockIdx.y * 32;
    int tx = threadIdx.x & 31, ty = threadIdx.x >> 5;
    #pragma unroll
    for (int j = 0; j < 4; j++)
        t[ty + j * 8][tx] = w[(size_t)(k0 + ty + j * 8) * N + n0 + tx];
    __syncthreads();
    #pragma unroll
    for (int j = 0; j < 4; j++)
        wT[(size_t)(n0 + ty + j * 8) * K + k0 + tx] = __float2half(t[tx][ty + j * 8]);
}

// ---------------- fused flash attention: Br=128, Bc=64, register P ----------------
#define LDQ 264                       // halves; pitch 528B -> ldsm conflict-free
#define AQ  0
#define AH0 (128 * LDQ)
#define AH1 (AH0 + 64 * LDQ)
#define ATTN_SMEM_BYTES ((AH1 + 64 * LDQ) * 2)   // 135168

__global__ void __launch_bounds__(256, 1) attn_kernel(const __half* __restrict__ h,
                                                      const float* __restrict__ x,
                                                      float* __restrict__ x1) {
    extern __shared__ __half sh[];
    uint32_t sbase = (uint32_t)__cvta_generic_to_shared(sh);

    int tid = threadIdx.x;
    int warp = tid >> 5, lane = tid & 31;
    int gr = lane >> 2, gc = lane & 3;
    int q0 = blockIdx.x * 128;
    int m0 = warp * 16;
    const __half* hb = h + (size_t)blockIdx.z * N_SEQ * D_DIM;

    // prologue: Q tile (128x256) + H tile 0 (64x256)
    {
        const __half* qsrc = hb + (size_t)q0 * D_DIM;
        #pragma unroll
        for (int i = 0; i < 16; i++) {
            int c = tid + i * 256;
            int row = c >> 5, ch = c & 31;
            cpa16(sh + AQ + row * LDQ + ch * 8, qsrc + (size_t)row * D_DIM + ch * 8);
        }
        #pragma unroll
        for (int i = 0; i < 8; i++) {
            int c = tid + i * 256;
            int row = c >> 5, ch = c & 31;
            cpa16(sh + AH0 + row * LDQ + ch * 8, hb + (size_t)row * D_DIM + ch * 8);
        }
        cpa_commit();
    }

    // per-lane ldmatrix address components
    uint32_t qaddr = sbase + (uint32_t)((AQ + (m0 + (lane & 15)) * LDQ + (lane >> 4) * 8) * 2);
    int sb_row = (lane & 7) + ((lane >> 4) & 1) * 8;   // + ntp*16  (key row)
    int sb_col = ((lane >> 3) & 1) * 8;                // + ks*16   (d col)
    int pv_row = (lane & 7) + ((lane >> 3) & 1) * 8;   // + ks*16   (key row)
    int pv_col = (lane >> 4) * 8;                      // + ntp*16  (d col)

    float oacc[32][4];
    #pragma unroll
    for (int i = 0; i < 32; i++)
        #pragma unroll
        for (int j = 0; j < 4; j++) oacc[i][j] = 0.f;
    float mr0 = -1e30f, mr1 = -1e30f, lr0 = 0.f, lr1 = 0.f;

    for (int jt = 0; jt < N_SEQ / 64; jt++) {
        cpa_wait<0>();
        __syncthreads();
        // prefetch next H tile (buffer read last at jt-1; barrier above protects it)
        if (jt + 1 < N_SEQ / 64) {
            __half* dst = sh + (((jt + 1) & 1) ? AH1 : AH0);
            const __half* src = hb + (size_t)(jt + 1) * 64 * D_DIM;
            #pragma unroll
            for (int i = 0; i < 8; i++) {
                int c = tid + i * 256;
                int row = c >> 5, ch = c & 31;
                cpa16(dst + row * LDQ + ch * 8, src + (size_t)row * D_DIM + ch * 8);
            }
            cpa_commit();
        }
        uint32_t HB = sbase + (uint32_t)(((jt & 1) ? AH1 : AH0) * 2);

        // ---- S = Q @ H^T : warp tile 16x64 ----
        float sacc[8][4];
        #pragma unroll
        for (int nt = 0; nt < 8; nt++)
            #pragma unroll
            for (int i = 0; i < 4; i++) sacc[nt][i] = 0.f;

        #pragma unroll
        for (int ks = 0; ks < 16; ks++) {
            uint32_t a[4];
            ldsm4(a, qaddr + ks * 32);
            #pragma unroll
            for (int ntp = 0; ntp < 4; ntp++) {
                uint32_t b[4];
                ldsm4(b, HB + (uint32_t)(((sb_row + ntp * 16) * LDQ + sb_col + ks * 16) * 2));
                mma_f16(sacc[2 * ntp],     a, b);
                mma_f16(sacc[2 * ntp + 1], a, b + 2);
            }
        }

        // ---- warp-local softmax (rows gr, gr+8) ----
        float mx0 = -1e30f, mx1 = -1e30f;
        #pragma unroll
        for (int nt = 0; nt < 8; nt++) {
            #pragma unroll
            for (int i = 0; i < 4; i++) sacc[nt][i] *= 0.0625f;
            mx0 = fmaxf(mx0, fmaxf(sacc[nt][0], sacc[nt][1]));
            mx1 = fmaxf(mx1, fmaxf(sacc[nt][2], sacc[nt][3]));
        }
        mx0 = fmaxf(mx0, __shfl_xor_sync(0xffffffffu, mx0, 1));
        mx0 = fmaxf(mx0, __shfl_xor_sync(0xffffffffu, mx0, 2));
        mx1 = fmaxf(mx1, __shfl_xor_sync(0xffffffffu, mx1, 1));
        mx1 = fmaxf(mx1, __shfl_xor_sync(0xffffffffu, mx1, 2));
        float mn0 = fmaxf(mr0, mx0), mn1 = fmaxf(mr1, mx1);
        float a0 = __expf(mr0 - mn0), a1 = __expf(mr1 - mn1);
        mr0 = mn0; mr1 = mn1;

        // P = exp(S-m) -> half2 A-frags + row sums
        uint32_t pa[16];
        float s0 = 0.f, s1 = 0.f;
        #pragma unroll
        for (int nt = 0; nt < 8; nt++) {
            float p0 = __expf(sacc[nt][0] - mn0);
            float p1 = __expf(sacc[nt][1] - mn0);
            float p2 = __expf(sacc[nt][2] - mn1);
            float p3 = __expf(sacc[nt][3] - mn1);
            s0 += p0 + p1; s1 += p2 + p3;
            int base = (nt >> 1) * 4 + (nt & 1) * 2;
            pa[base]     = pack_f16x2(p0, p1);
            pa[base + 1] = pack_f16x2(p2, p3);
        }
        s0 += __shfl_xor_sync(0xffffffffu, s0, 1);
        s0 += __shfl_xor_sync(0xffffffffu, s0, 2);
        s1 += __shfl_xor_sync(0xffffffffu, s1, 1);
        s1 += __shfl_xor_sync(0xffffffffu, s1, 2);
        lr0 = a0 * lr0 + s0;
        lr1 = a1 * lr1 + s1;

        // rescale O (skip when warp-uniformly unchanged)
        if (!__all_sync(0xffffffffu, (a0 == 1.f) & (a1 == 1.f))) {
            #pragma unroll
            for (int nt = 0; nt < 32; nt++) {
                oacc[nt][0] *= a0; oacc[nt][1] *= a0;
                oacc[nt][2] *= a1; oacc[nt][3] *= a1;
            }
        }

        // ---- O += P @ H : 16 rows x 256 cols per warp ----
        #pragma unroll
        for (int ks = 0; ks < 4; ks++) {
            const uint32_t* af = &pa[ks * 4];
            #pragma unroll
            for (int ntp = 0; ntp < 16; ntp++) {
                uint32_t b[4];
                ldsm4t(b, HB + (uint32_t)(((ks * 16 + pv_row) * LDQ + ntp * 16 + pv_col) * 2));
                mma_f16(oacc[2 * ntp],     af, b);
                mma_f16(oacc[2 * ntp + 1], af, b + 2);
            }
        }
    }

    // ---- epilogue: O/l + residual ----
    float inv0 = 1.0f / lr0, inv1 = 1.0f / lr1;
    int r0 = q0 + m0 + gr, r1 = r0 + 8;
    const float* xb = x  + (size_t)blockIdx.z * N_SEQ * D_DIM;
    float*       ob = x1 + (size_t)blockIdx.z * N_SEQ * D_DIM;
    #pragma unroll
    for (int nt = 0; nt < 32; nt++) {
        int col = nt * 8 + 2 * gc;
        float2 xv0 = *(const float2*)&xb[(size_t)r0 * D_DIM + col];
        float2 xv1 = *(const float2*)&xb[(size_t)r1 * D_DIM + col];
        *(float2*)&ob[(size_t)r0 * D_DIM + col] =
            make_float2(oacc[nt][0] * inv0 + xv0.x, oacc[nt][1] * inv0 + xv0.y);
        *(float2*)&ob[(size_t)r1 * D_DIM + col] =
            make_float2(oacc[nt][2] * inv1 + xv1.x, oacc[nt][3] * inv1 + xv1.y);
    }
}

// ---------------- fp16 GEMM: C[M,N] = A[M,K] @ Bt[N,K]^T (cp.async 2-stage) ----------------
#define GP 72
#define GAS0 0
#define GBS0 9216
#define GAS1 18432
#define GBS1 27648
#define GEMM_SMEM_BYTES (36864 * 2)

__global__ void __launch_bounds__(256, 2) gemm_f16(const __half* __restrict__ A,
                                                   const __half* __restrict__ Bt,
                                                   void* __restrict__ Cv,
                                                   const float* __restrict__ bias,
                                                   const float* __restrict__ res,
                                                   int N, int K, int do_relu, int out_half) {
    extern __shared__ __half sh[];
    int tid = threadIdx.x;
    int warp = tid >> 5, lane = tid & 31;
    int m0 = blockIdx.x * 128, n0 = blockIdx.y * 128;
    int wm = (warp >> 2) * 64, wn = (warp & 3) * 32;
    int gr = lane >> 2, gc = lane & 3;

    float acc[4][4][4];
    #pragma unroll
    for (int i = 0; i < 4; i++)
        #pragma unroll
        for (int j = 0; j < 4; j++)
            #pragma unroll
            for (int v = 0; v < 4; v++) acc[i][j][v] = 0.f;

    {
        #pragma unroll
        for (int i = 0; i < 4; i++) {
            int c = tid + i * 256;
            int row = c >> 3, ch = c & 7;
            cpa16(sh + GAS0 + row * GP + ch * 8, A + (size_t)(m0 + row) * K + ch * 8);
        }
        #pragma unroll
        for (int i = 0; i < 4; i++) {
            int c = tid + i * 256;
            int row = c >> 3, ch = c & 7;
            cpa16(sh + GBS0 + row * GP + ch * 8, Bt + (size_t)(n0 + row) * K + ch * 8);
        }
        cpa_commit();
    }

    int ntiles = K >> 6;
    for (int kt = 0; kt < ntiles; kt++) {
        if (kt + 1 < ntiles) {
            int k0 = (kt + 1) * 64;
            __half* as = sh + (((kt + 1) & 1) ? GAS1 : GAS0);
            __half* bs = sh + (((kt + 1) & 1) ? GBS1 : GBS0);
            #pragma unroll
            for (int i = 0; i < 4; i++) {
                int c = tid + i * 256;
                int row = c >> 3, ch = c & 7;
                cpa16(as + row * GP + ch * 8, A + (size_t)(m0 + row) * K + k0 + ch * 8);
            }
            #pragma unroll
            for (int i = 0; i < 4; i++) {
                int c = tid + i * 256;
                int row = c >> 3, ch = c & 7;
                cpa16(bs + row * GP + ch * 8, Bt + (size_t)(n0 + row) * K + k0 + ch * 8);
            }
            cpa_commit();
            cpa_wait<1>();
        } else {
            cpa_wait<0>();
        }
        __syncthreads();

        const __half* AS = sh + ((kt & 1) ? GAS1 : GAS0);
        const __half* BS = sh + ((kt & 1) ? GBS1 : GBS0);

        #pragma unroll
        for (int ks = 0; ks < 4; ks++) {
            int kk = ks * 16;
            uint32_t af[4][4], bf[4][2];
            #pragma unroll
            for (int mt = 0; mt < 4; mt++) {
                const __half* Ar = AS + (wm + mt * 16 + gr) * GP + kk + 2 * gc;
                af[mt][0] = ldu32(Ar);
                af[mt][1] = ldu32(Ar + 8 * GP);
                af[mt][2] = ldu32(Ar + 8);
                af[mt][3] = ldu32(Ar + 8 * GP + 8);
            }
            #pragma unroll
            for (int nt = 0; nt < 4; nt++) {
                const __half* Br = BS + (wn + nt * 8 + gr) * GP + kk + 2 * gc;
                bf[nt][0] = ldu32(Br);
                bf[nt][1] = ldu32(Br + 8);
            }
            #pragma unroll
            for (int mt = 0; mt < 4; mt++)
                #pragma unroll
                for (int nt = 0; nt < 4; nt++)
                    mma_f16(acc[mt][nt], af[mt], bf[nt]);
        }
        __syncthreads();
    }

    #pragma unroll
    for (int mt = 0; mt < 4; mt++) {
        #pragma unroll
        for (int nt = 0; nt < 4; nt++) {
            int col = n0 + wn + nt * 8 + 2 * gc;
            float b0 = bias[col], b1 = bias[col + 1];
            #pragma unroll
            for (int hh = 0; hh < 2; hh++) {
                int row = m0 + wm + mt * 16 + gr + hh * 8;
                float c0 = acc[mt][nt][2 * hh]     + b0;
                float c1 = acc[mt][nt][2 * hh + 1] + b1;
                if (do_relu) { c0 = fmaxf(c0, 0.f); c1 = fmaxf(c1, 0.f); }
                if (res) {
                    float2 r2 = *(const float2*)(res + (size_t)row * N + col);
                    c0 += r2.x; c1 += r2.y;
                }
                if (out_half) {
                    *(__half2*)((__half*)Cv + (size_t)row * N + col) = __floats2half2_rn(c0, c1);
                } else {
                    *(float2*)((float*)Cv + (size_t)row * N + col) = make_float2(c0, c1);
                }
            }
        }
    }
}

// ---------------- launch ----------------
extern "C" void kernel_launch(void* const* d_in, const int* in_sizes, int n_in,
                              void* d_out, int out_size) {
    const float* x   = (const float*)d_in[0];
    const float* w1  = (const float*)d_in[1];
    const float* b1  = (const float*)d_in[2];
    const float* w2  = (const float*)d_in[3];
    const float* b2  = (const float*)d_in[4];
    const float* g1  = (const float*)d_in[5];
    const float* be1 = (const float*)d_in[6];
    const float* g2  = (const float*)d_in[7];
    const float* be2 = (const float*)d_in[8];
    float* out = (float*)d_out;

    __half *hh, *h2h, *mid, *w1T, *w2T;
    float *x1;
    cudaGetSymbolAddress((void**)&hh,  g_hh);
    cudaGetSymbolAddress((void**)&x1,  g_x1);
    cudaGetSymbolAddress((void**)&h2h, g_h2h);
    cudaGetSymbolAddress((void**)&mid, g_mid);
    cudaGetSymbolAddress((void**)&w1T, g_w1T);
    cudaGetSymbolAddress((void**)&w2T, g_w2T);

    cudaFuncSetAttribute(attn_kernel, cudaFuncAttributeMaxDynamicSharedMemorySize,
                         ATTN_SMEM_BYTES);
    cudaFuncSetAttribute(gemm_f16, cudaFuncAttributeMaxDynamicSharedMemorySize,
                         GEMM_SMEM_BYTES);

    // weight prep
    wt_kernel<<<dim3(HID / 32, D_DIM / 32), 256>>>(w1, w1T, D_DIM, HID);
    wt_kernel<<<dim3(D_DIM / 32, HID / 32), 256>>>(w2, w2T, HID, D_DIM);

    // Sublayer 1
    ln_kernel<<<ROWS, 256>>>(x, g1, be1, hh);
    attn_kernel<<<dim3(N_SEQ / 128, 1, BATCH), 256, ATTN_SMEM_BYTES>>>(hh, x, x1);

    // Sublayer 2
    ln_kernel<<<ROWS, 256>>>(x1, g2, be2, h2h);
    gemm_f16<<<dim3(ROWS / 128, HID / 128), 256, GEMM_SMEM_BYTES>>>(
        h2h, w1T, mid, b1, nullptr, HID, D_DIM, 1, 1);
    gemm_f16<<<dim3(ROWS / 128, D_DIM / 128), 256, GEMM_SMEM_BYTES>>>(
        mid, w2T, out, b2, x1, D_DIM, HID, 0, 0);
}